// round 15
// baseline (speedup 1.0000x reference)
#include <cuda_runtime.h>

// sPCEN: per-row constant-coefficient EMA scan + pointwise transform.
// Warp-autonomous: global warp id -> (row, span); each warp owns 3200 outputs
// (+256-sample zero-init warm-up; span holding element 0 is exact).
// Per 128-elem tile: LDG.128 -> 32-lane shuffle scan (u-space, lane mult a^4)
// -> transform -> STG.128. Cross-tile carry: c = a^128*c + tile_total.
// Main loop NOT unrolled (R12 lesson: unroll-5 -> 54 regs -> occupancy loss).
//
// ema_0 = x_0 ; ema_t = a*ema_{t-1} + s*x_t , a = 1-s, s = clip(ema_weights,0,1)
// out = (x * (EPS+ema)^{-alpha_c} + d)^{1/root_c} - d^{1/root_c}

#define T_LEN   16000
#define SPAN    3200             // outputs per warp (5 spans per row)
#define SPANS   5
#define TILE    128
#define MAINT   (SPAN / TILE)    // 25 output tiles
#define WARMT   2                // 256-sample warm-up
#define THREADS 256              // 8 independent warps per CTA
#define WPB     (THREADS / 32)

__device__ __forceinline__ float sqrt_approx(float v) {
    float r;
    asm("sqrt.approx.f32 %0, %1;" : "=f"(r) : "f"(v));
    return r;
}

#define SCAN5(tl) do {                                                         \
    float _u;                                                                  \
    _u = __shfl_up_sync(0xffffffffu, tl, 1);  if (lane >= 1)  tl = fmaf(a4,  _u, tl); \
    _u = __shfl_up_sync(0xffffffffu, tl, 2);  if (lane >= 2)  tl = fmaf(a8,  _u, tl); \
    _u = __shfl_up_sync(0xffffffffu, tl, 4);  if (lane >= 4)  tl = fmaf(a16, _u, tl); \
    _u = __shfl_up_sync(0xffffffffu, tl, 8);  if (lane >= 8)  tl = fmaf(a32, _u, tl); \
    _u = __shfl_up_sync(0xffffffffu, tl, 16); if (lane >= 16) tl = fmaf(a64, _u, tl); \
} while (0)

__global__ void __launch_bounds__(THREADS, 8)
spcen_warp_kernel(const float* __restrict__ x,
                  const float* __restrict__ alpha,
                  const float* __restrict__ delta,
                  const float* __restrict__ root,
                  const float* __restrict__ ew,
                  float* __restrict__ out, int C)
{
    const int lane = threadIdx.x & 31;
    const int wg   = blockIdx.x * WPB + (threadIdx.x >> 5); // global warp id
    const int row  = wg / SPANS;
    const int sp   = wg - row * SPANS;
    const int c    = row % C;

    const float s       = fminf(fmaxf(ew[c], 0.0f), 1.0f);
    const float a       = 1.0f - s;
    const float s_inv   = 1.0f / fmaxf(s, 1e-30f);
    const float alpha_c = fminf(alpha[c], 1.0f);
    const float d       = delta[c];
    const float rootc   = fmaxf(root[c], 1.0f);
    const float r       = 1.0f / rootc;

    const float* __restrict__ xrow = x   + (size_t)row * T_LEN;
    float*       __restrict__ orow = out + (size_t)row * T_LEN;

    const int  start = sp * SPAN;               // first output element
    const bool zwarp = (sp == 0);               // span containing element 0

    // powers of a
    const float a2   = a * a;
    const float a4   = a2 * a2;
    const float a8   = a4 * a4;
    const float a16  = a8 * a8;
    const float a32  = a16 * a16;
    const float a64  = a32 * a32;
    const float a128 = a64 * a64;
    // a^{4*lane}
    float a4l = 1.0f;
    { float mp = a4; int b = lane;
      #pragma unroll
      for (int q = 0; q < 5; q++) { if (b & 1) a4l *= mp; mp *= mp; b >>= 1; } }

    const bool  use_sqrt = (r == 0.5f);
    const float dr = use_sqrt ? sqrt_approx(d) : __powf(d, r);

    float carry = 0.0f;

    // ===== warm-up: 2 tiles, scan only (span 0 skips: all-zero history) =====
    if (!zwarp) {
        const float* xw = xrow + start - WARMT * TILE + lane * 4;
        #pragma unroll
        for (int t = 0; t < WARMT; t++) {
            float4 v = *(const float4*)(xw + t * TILE);
            float tl = v.x;
            tl = fmaf(a, tl, v.y);
            tl = fmaf(a, tl, v.z);
            tl = fmaf(a, tl, v.w);
            SCAN5(tl);
            float total = __shfl_sync(0xffffffffu, tl, 31);
            carry = fmaf(a128, carry, total);
        }
    }

    // ===== main: 25 tiles, scan + transform + store (no unroll) =====
    const float* xp = xrow + start + lane * 4;
    float*       op = orow + start + lane * 4;

    float4 v = *(const float4*)xp;              // tile 0 (always in-bounds)

    #pragma unroll 1
    for (int t = 0; t < MAINT; t++) {
        float4 vn;
        if (t + 1 < MAINT) vn = *(const float4*)(xp + (t + 1) * TILE);

        const bool spec = zwarp && (t == 0) && (lane == 0);   // global elem 0

        // lane-local 4-elem u-space reduction (zero-init)
        float tl = spec ? (v.x * s_inv) : v.x;
        tl = fmaf(a, tl, v.y);
        tl = fmaf(a, tl, v.z);
        tl = fmaf(a, tl, v.w);
        SCAN5(tl);

        float ex    = __shfl_up_sync(0xffffffffu, tl, 1);
        if (lane == 0) ex = 0.0f;
        float total = __shfl_sync(0xffffffffu, tl, 31);

        float base = fmaf(a4l, carry, ex);      // u entering lane's 4 elems
        float4 o;
        float uu = fmaf(a, base, v.x);
        if (spec) uu = v.x * s_inv;
        {
            float pin = fmaf(s, uu, 1e-6f);     // eps + ema
            float pw  = __powf(pin, -alpha_c);
            float vv  = fmaf(v.x, pw, d);
            o.x = use_sqrt ? (sqrt_approx(vv) - dr) : (__powf(vv, r) - dr);
        }
        uu = fmaf(a, uu, v.y);
        {
            float pin = fmaf(s, uu, 1e-6f);
            float pw  = __powf(pin, -alpha_c);
            float vv  = fmaf(v.y, pw, d);
            o.y = use_sqrt ? (sqrt_approx(vv) - dr) : (__powf(vv, r) - dr);
        }
        uu = fmaf(a, uu, v.z);
        {
            float pin = fmaf(s, uu, 1e-6f);
            float pw  = __powf(pin, -alpha_c);
            float vv  = fmaf(v.z, pw, d);
            o.z = use_sqrt ? (sqrt_approx(vv) - dr) : (__powf(vv, r) - dr);
        }
        uu = fmaf(a, uu, v.w);
        {
            float pin = fmaf(s, uu, 1e-6f);
            float pw  = __powf(pin, -alpha_c);
            float vv  = fmaf(v.w, pw, d);
            o.w = use_sqrt ? (sqrt_approx(vv) - dr) : (__powf(vv, r) - dr);
        }
        __stcs((float4*)(op + t * TILE), o);

        carry = fmaf(a128, carry, total);
        v = vn;
    }
}

extern "C" void kernel_launch(void* const* d_in, const int* in_sizes, int n_in,
                              void* d_out, int out_size) {
    const float* x     = (const float*)d_in[0];
    const float* alpha = (const float*)d_in[1];
    const float* delta = (const float*)d_in[2];
    const float* root  = (const float*)d_in[3];
    const float* ew    = (const float*)d_in[4];
    float* out = (float*)d_out;

    const int C     = in_sizes[1];
    const int rows  = in_sizes[0] / T_LEN;          // B*C
    const int warps = rows * SPANS;                 // 20480
    const int grid  = (warps + WPB - 1) / WPB;      // 2560
    spcen_warp_kernel<<<grid, THREADS>>>(x, alpha, delta, root, ew, out, C);
}

// round 16
// speedup vs baseline: 1.5652x; 1.5652x over previous
#include <cuda_runtime.h>

// sPCEN: per-row constant-coefficient EMA scan + pointwise transform.
// Warp-autonomous: global warp id -> (row, span); each warp owns 3200 outputs
// (+256-sample zero-init warm-up; span holding element 0 is exact).
// Per 128-elem tile: LDG.128 -> 32-lane shuffle scan (u-space, lane mult a^4)
// -> transform -> STG.128. Cross-tile carry: c = a^128*c + tile_total.
// NO min-blocks launch bound (R15 lesson: (256,8) forced 32-reg cap -> spills
// -> L1 61%, 2x issue). NO unroll pragma (R12 lesson: unroll-5 -> 54 regs).
//
// ema_0 = x_0 ; ema_t = a*ema_{t-1} + s*x_t , a = 1-s, s = clip(ema_weights,0,1)
// out = (x * (EPS+ema)^{-alpha_c} + d)^{1/root_c} - d^{1/root_c}

#define T_LEN   16000
#define SPAN    3200             // outputs per warp (5 spans per row)
#define SPANS   5
#define TILE    128
#define MAINT   (SPAN / TILE)    // 25 output tiles
#define WARMT   2                // 256-sample warm-up
#define THREADS 256              // 8 independent warps per CTA
#define WPB     (THREADS / 32)

__device__ __forceinline__ float sqrt_approx(float v) {
    float r;
    asm("sqrt.approx.f32 %0, %1;" : "=f"(r) : "f"(v));
    return r;
}

#define SCAN5(tl) do {                                                         \
    float _u;                                                                  \
    _u = __shfl_up_sync(0xffffffffu, tl, 1);  if (lane >= 1)  tl = fmaf(a4,  _u, tl); \
    _u = __shfl_up_sync(0xffffffffu, tl, 2);  if (lane >= 2)  tl = fmaf(a8,  _u, tl); \
    _u = __shfl_up_sync(0xffffffffu, tl, 4);  if (lane >= 4)  tl = fmaf(a16, _u, tl); \
    _u = __shfl_up_sync(0xffffffffu, tl, 8);  if (lane >= 8)  tl = fmaf(a32, _u, tl); \
    _u = __shfl_up_sync(0xffffffffu, tl, 16); if (lane >= 16) tl = fmaf(a64, _u, tl); \
} while (0)

__global__ void __launch_bounds__(THREADS)
spcen_warp_kernel(const float* __restrict__ x,
                  const float* __restrict__ alpha,
                  const float* __restrict__ delta,
                  const float* __restrict__ root,
                  const float* __restrict__ ew,
                  float* __restrict__ out, int C)
{
    const int lane = threadIdx.x & 31;
    const int wg   = blockIdx.x * WPB + (threadIdx.x >> 5); // global warp id
    const int row  = wg / SPANS;
    const int sp   = wg - row * SPANS;
    const int c    = row % C;

    const float s       = fminf(fmaxf(ew[c], 0.0f), 1.0f);
    const float a       = 1.0f - s;
    const float s_inv   = 1.0f / fmaxf(s, 1e-30f);
    const float alpha_c = fminf(alpha[c], 1.0f);
    const float d       = delta[c];
    const float rootc   = fmaxf(root[c], 1.0f);
    const float r       = 1.0f / rootc;

    const float* __restrict__ xrow = x   + (size_t)row * T_LEN;
    float*       __restrict__ orow = out + (size_t)row * T_LEN;

    const int  start = sp * SPAN;               // first output element
    const bool zwarp = (sp == 0);               // span containing element 0

    // powers of a
    const float a2   = a * a;
    const float a4   = a2 * a2;
    const float a8   = a4 * a4;
    const float a16  = a8 * a8;
    const float a32  = a16 * a16;
    const float a64  = a32 * a32;
    const float a128 = a64 * a64;
    // a^{4*lane}
    float a4l = 1.0f;
    { float mp = a4; int b = lane;
      #pragma unroll
      for (int q = 0; q < 5; q++) { if (b & 1) a4l *= mp; mp *= mp; b >>= 1; } }

    const bool  use_sqrt = (r == 0.5f);
    const float dr = use_sqrt ? sqrt_approx(d) : __powf(d, r);

    float carry = 0.0f;

    // ===== warm-up: 2 tiles, scan only (span 0 skips: all-zero history) =====
    if (!zwarp) {
        const float* xw = xrow + start - WARMT * TILE + lane * 4;
        #pragma unroll
        for (int t = 0; t < WARMT; t++) {
            float4 v = *(const float4*)(xw + t * TILE);
            float tl = v.x;
            tl = fmaf(a, tl, v.y);
            tl = fmaf(a, tl, v.z);
            tl = fmaf(a, tl, v.w);
            SCAN5(tl);
            float total = __shfl_sync(0xffffffffu, tl, 31);
            carry = fmaf(a128, carry, total);
        }
    }

    // ===== main: 25 tiles, scan + transform + store =====
    const float* xp = xrow + start + lane * 4;
    float*       op = orow + start + lane * 4;

    float4 v = *(const float4*)xp;              // tile 0 (always in-bounds)

    for (int t = 0; t < MAINT; t++) {
        float4 vn;
        if (t + 1 < MAINT) vn = *(const float4*)(xp + (t + 1) * TILE);

        const bool spec = zwarp && (t == 0) && (lane == 0);   // global elem 0

        // lane-local 4-elem u-space reduction (zero-init)
        float tl = spec ? (v.x * s_inv) : v.x;
        tl = fmaf(a, tl, v.y);
        tl = fmaf(a, tl, v.z);
        tl = fmaf(a, tl, v.w);
        SCAN5(tl);

        float ex    = __shfl_up_sync(0xffffffffu, tl, 1);
        if (lane == 0) ex = 0.0f;
        float total = __shfl_sync(0xffffffffu, tl, 31);

        float base = fmaf(a4l, carry, ex);      // u entering lane's 4 elems
        float4 o;
        float uu = fmaf(a, base, v.x);
        if (spec) uu = v.x * s_inv;
        {
            float pin = fmaf(s, uu, 1e-6f);     // eps + ema
            float pw  = __powf(pin, -alpha_c);
            float vv  = fmaf(v.x, pw, d);
            o.x = use_sqrt ? (sqrt_approx(vv) - dr) : (__powf(vv, r) - dr);
        }
        uu = fmaf(a, uu, v.y);
        {
            float pin = fmaf(s, uu, 1e-6f);
            float pw  = __powf(pin, -alpha_c);
            float vv  = fmaf(v.y, pw, d);
            o.y = use_sqrt ? (sqrt_approx(vv) - dr) : (__powf(vv, r) - dr);
        }
        uu = fmaf(a, uu, v.z);
        {
            float pin = fmaf(s, uu, 1e-6f);
            float pw  = __powf(pin, -alpha_c);
            float vv  = fmaf(v.z, pw, d);
            o.z = use_sqrt ? (sqrt_approx(vv) - dr) : (__powf(vv, r) - dr);
        }
        uu = fmaf(a, uu, v.w);
        {
            float pin = fmaf(s, uu, 1e-6f);
            float pw  = __powf(pin, -alpha_c);
            float vv  = fmaf(v.w, pw, d);
            o.w = use_sqrt ? (sqrt_approx(vv) - dr) : (__powf(vv, r) - dr);
        }
        __stcs((float4*)(op + t * TILE), o);

        carry = fmaf(a128, carry, total);
        v = vn;
    }
}

extern "C" void kernel_launch(void* const* d_in, const int* in_sizes, int n_in,
                              void* d_out, int out_size) {
    const float* x     = (const float*)d_in[0];
    const float* alpha = (const float*)d_in[1];
    const float* delta = (const float*)d_in[2];
    const float* root  = (const float*)d_in[3];
    const float* ew    = (const float*)d_in[4];
    float* out = (float*)d_out;

    const int C     = in_sizes[1];
    const int rows  = in_sizes[0] / T_LEN;          // B*C
    const int warps = rows * SPANS;                 // 20480
    const int grid  = (warps + WPB - 1) / WPB;      // 2560
    spcen_warp_kernel<<<grid, THREADS>>>(x, alpha, delta, root, ew, out, C);
}

// round 17
// speedup vs baseline: 1.6010x; 1.0229x over previous
#include <cuda_runtime.h>

// sPCEN: per-row constant-coefficient EMA scan + pointwise transform.
// Warp-autonomous: global warp id -> (row, span); each warp owns 3200 outputs
// (+256-sample zero-init warm-up; span 0 is EXACT via carry = x0/s init).
// Per 128-elem tile: LDG.128 -> 32-lane shuffle scan (u-space, lane mult a^4)
// -> transform -> STG.128. Cross-tile carry: c = a^128*c + tile_total.
// use_sqrt hoisted to a uniform loop-level branch (no per-element dual path).
//
// ema_0 = x_0 ; ema_t = a*ema_{t-1} + s*x_t , a = 1-s, s = clip(ema_weights,0,1)
// out = (x * (EPS+ema)^{-alpha_c} + d)^{1/root_c} - d^{1/root_c}

#define T_LEN   16000
#define SPAN    3200             // outputs per warp (5 spans per row)
#define SPANS   5
#define TILE    128
#define MAINT   (SPAN / TILE)    // 25 output tiles
#define WARMT   2                // 256-sample warm-up
#define THREADS 256              // 8 independent warps per CTA
#define WPB     (THREADS / 32)

__device__ __forceinline__ float sqrt_approx(float v) {
    float r; asm("sqrt.approx.f32 %0, %1;" : "=f"(r) : "f"(v)); return r;
}
__device__ __forceinline__ float lg2f(float v) {
    float r; asm("lg2.approx.f32 %0, %1;" : "=f"(r) : "f"(v)); return r;
}
__device__ __forceinline__ float ex2f(float v) {
    float r; asm("ex2.approx.f32 %0, %1;" : "=f"(r) : "f"(v)); return r;
}

#define SCAN5(tl) do {                                                         \
    float _u;                                                                  \
    _u = __shfl_up_sync(0xffffffffu, tl, 1);  if (lane >= 1)  tl = fmaf(a4,  _u, tl); \
    _u = __shfl_up_sync(0xffffffffu, tl, 2);  if (lane >= 2)  tl = fmaf(a8,  _u, tl); \
    _u = __shfl_up_sync(0xffffffffu, tl, 4);  if (lane >= 4)  tl = fmaf(a16, _u, tl); \
    _u = __shfl_up_sync(0xffffffffu, tl, 8);  if (lane >= 8)  tl = fmaf(a32, _u, tl); \
    _u = __shfl_up_sync(0xffffffffu, tl, 16); if (lane >= 16) tl = fmaf(a64, _u, tl); \
} while (0)

// One element: advance u, compute output via TAIL(vv)
#define ELEM(xv, dst, TAIL) do {                                               \
    uu = fmaf(a, uu, xv);                                                      \
    float pin = fmaf(s, uu, 1e-6f);                                            \
    float pw  = ex2f(nalpha * lg2f(pin));                                      \
    float vv  = fmaf(xv, pw, d);                                               \
    dst = TAIL(vv) - dr;                                                       \
} while (0)

#define MAIN_LOOP(TAIL) do {                                                   \
    float4 v = *(const float4*)xp;                                             \
    for (int t = 0; t < MAINT; t++) {                                          \
        float4 vn;                                                             \
        if (t + 1 < MAINT) vn = *(const float4*)(xp + (t + 1) * TILE);         \
        float tl = v.x;                                                        \
        tl = fmaf(a, tl, v.y);                                                 \
        tl = fmaf(a, tl, v.z);                                                 \
        tl = fmaf(a, tl, v.w);                                                 \
        SCAN5(tl);                                                             \
        float ex = __shfl_up_sync(0xffffffffu, tl, 1);                         \
        if (lane == 0) ex = 0.0f;                                              \
        float total = __shfl_sync(0xffffffffu, tl, 31);                        \
        float uu = fmaf(a4l, carry, ex);   /* u entering lane's elems */       \
        float4 o;                                                              \
        ELEM(v.x, o.x, TAIL);                                                  \
        ELEM(v.y, o.y, TAIL);                                                  \
        ELEM(v.z, o.z, TAIL);                                                  \
        ELEM(v.w, o.w, TAIL);                                                  \
        __stcs((float4*)(op + t * TILE), o);                                   \
        carry = fmaf(a128, carry, total);                                      \
        v = vn;                                                                \
    }                                                                          \
} while (0)

#define TAIL_SQRT(vv) sqrt_approx(vv)
#define TAIL_POW(vv)  ex2f(r * lg2f(vv))

__global__ void __launch_bounds__(THREADS)
spcen_warp_kernel(const float* __restrict__ x,
                  const float* __restrict__ alpha,
                  const float* __restrict__ delta,
                  const float* __restrict__ root,
                  const float* __restrict__ ew,
                  float* __restrict__ out, int C)
{
    const int lane = threadIdx.x & 31;
    const int wg   = blockIdx.x * WPB + (threadIdx.x >> 5); // global warp id
    const int row  = wg / SPANS;
    const int sp   = wg - row * SPANS;
    const int c    = row % C;

    const float s       = fminf(fmaxf(ew[c], 0.0f), 1.0f);
    const float a       = 1.0f - s;
    const float alpha_c = fminf(alpha[c], 1.0f);
    const float nalpha  = -alpha_c;
    const float d       = delta[c];
    const float rootc   = fmaxf(root[c], 1.0f);
    const float r       = 1.0f / rootc;

    const float* __restrict__ xrow = x   + (size_t)row * T_LEN;
    float*       __restrict__ orow = out + (size_t)row * T_LEN;

    const int start = sp * SPAN;                // first output element

    // powers of a
    const float a2   = a * a;
    const float a4   = a2 * a2;
    const float a8   = a4 * a4;
    const float a16  = a8 * a8;
    const float a32  = a16 * a16;
    const float a64  = a32 * a32;
    const float a128 = a64 * a64;
    // a^{4*lane}
    float a4l = 1.0f;
    { float mp = a4; int b = lane;
      #pragma unroll
      for (int q = 0; q < 5; q++) { if (b & 1) a4l *= mp; mp *= mp; b >>= 1; } }

    const bool  use_sqrt = (r == 0.5f);
    const float dr = use_sqrt ? sqrt_approx(d) : ex2f(r * lg2f(d));

    float carry;
    if (sp == 0) {
        // Exact element-0 init: carry = x0/s makes the plain scan reproduce
        // ema_0 = x_0 (uses a + s = 1; see derivation in round notes).
        carry = xrow[0] / fmaxf(s, 1e-30f);
    } else {
        // 2 warm-up tiles, scan only (zero-init truncation ~6e-7)
        carry = 0.0f;
        const float* xw = xrow + start - WARMT * TILE + lane * 4;
        #pragma unroll
        for (int t = 0; t < WARMT; t++) {
            float4 v = *(const float4*)(xw + t * TILE);
            float tl = v.x;
            tl = fmaf(a, tl, v.y);
            tl = fmaf(a, tl, v.z);
            tl = fmaf(a, tl, v.w);
            SCAN5(tl);
            float total = __shfl_sync(0xffffffffu, tl, 31);
            carry = fmaf(a128, carry, total);
        }
    }

    const float* xp = xrow + start + lane * 4;
    float*       op = orow + start + lane * 4;

    if (use_sqrt) {
        MAIN_LOOP(TAIL_SQRT);
    } else {
        MAIN_LOOP(TAIL_POW);
    }
}

extern "C" void kernel_launch(void* const* d_in, const int* in_sizes, int n_in,
                              void* d_out, int out_size) {
    const float* x     = (const float*)d_in[0];
    const float* alpha = (const float*)d_in[1];
    const float* delta = (const float*)d_in[2];
    const float* root  = (const float*)d_in[3];
    const float* ew    = (const float*)d_in[4];
    float* out = (float*)d_out;

    const int C     = in_sizes[1];
    const int rows  = in_sizes[0] / T_LEN;          // B*C
    const int warps = rows * SPANS;                 // 20480
    const int grid  = (warps + WPB - 1) / WPB;      // 2560
    spcen_warp_kernel<<<grid, THREADS>>>(x, alpha, delta, root, ew, out, C);
}